// round 8
// baseline (speedup 1.0000x reference)
#include <cuda_runtime.h>
#include <cuda_fp16.h>
#include <cstdint>

#define NNODES 100000
#define FIN    128
#define FHID   64
#define MHID   128
#define ELLW   96

__device__ int    g_cnt[NNODES];
__device__ int    g_ell[(size_t)NNODES * ELLW];
__device__ float  g_dinv[NNODES];
__device__ __align__(16) __half g_hs[NNODES * FHID];     // gemm outputs, pre-scaled, fp16
__device__ float  g_bufC[NNODES * FHID];                 // h1 / out (fp32)
__device__ __align__(16) __half g_P[(size_t)NNODES * MHID];
__device__ __align__(16) __half g_Q[(size_t)NNODES * MHID];
// transposed fp16 weights: [n][k]
__device__ __align__(16) __half g_W1t[64 * 128];
__device__ __align__(16) __half g_W2t[64 * 64];
__device__ __align__(16) __half g_WPQt[256 * 64];

__device__ __forceinline__ float4 unpack_h4(uint2 u) {
    __half2 lo = *reinterpret_cast<__half2*>(&u.x);
    __half2 hi = *reinterpret_cast<__half2*>(&u.y);
    float2 a = __half22float2(lo);
    float2 b = __half22float2(hi);
    return make_float4(a.x, a.y, b.x, b.y);
}

__device__ __forceinline__ void mma16816(float d[4],
                                         unsigned a0, unsigned a1, unsigned a2, unsigned a3,
                                         unsigned b0, unsigned b1) {
    asm volatile("mma.sync.aligned.m16n8k16.row.col.f32.f16.f16.f32 "
                 "{%0,%1,%2,%3}, {%4,%5,%6,%7}, {%8,%9}, {%0,%1,%2,%3};"
                 : "+f"(d[0]), "+f"(d[1]), "+f"(d[2]), "+f"(d[3])
                 : "r"(a0), "r"(a1), "r"(a2), "r"(a3), "r"(b0), "r"(b1));
}

// store float4 as 2x half2 (8 bytes) to smem
__device__ __forceinline__ void st_h4(__half* p, float4 v) {
    __half2 lo = __floats2half2_rn(v.x, v.y);
    __half2 hi = __floats2half2_rn(v.z, v.w);
    uint2 u;
    u.x = *reinterpret_cast<unsigned*>(&lo);
    u.y = *reinterpret_cast<unsigned*>(&hi);
    *reinterpret_cast<uint2*>(p) = u;
}

// ---- setup ----
__global__ void k_zero() {
    int i = blockIdx.x * blockDim.x + threadIdx.x;
    if (i < NNODES) g_cnt[i] = 0;
}

__global__ void k_fill(const int* __restrict__ src, const int* __restrict__ dst, int E) {
    int e = blockIdx.x * blockDim.x + threadIdx.x;
    if (e >= E) return;
    int s = src[e], d = dst[e];
    int pos = atomicAdd(&g_cnt[d], 1);
    if (pos < ELLW) g_ell[(size_t)d * ELLW + pos] = s;
}

__global__ void k_dinv() {
    int v = blockIdx.x * blockDim.x + threadIdx.x;
    if (v < NNODES) g_dinv[v] = rsqrtf(fmaxf((float)(g_cnt[v] + 1), 1e-12f));
}

// ---- convert+transpose weights to fp16 [n][k] ----
__global__ void k_prep(const float* __restrict__ W1, const float* __restrict__ W2,
                       const float* __restrict__ fc1W) {
    int i = blockIdx.x * blockDim.x + threadIdx.x;
    if (i < 64 * 128) {                          // W1t[n][k], n<64, k<128
        int n = i >> 7, k = i & 127;
        g_W1t[i] = __float2half(W1[k * 64 + n]);
    } else if (i < 64 * 128 + 64 * 64) {         // W2t[n][k], n<64, k<64
        int j = i - 64 * 128;
        int n = j >> 6, k = j & 63;
        g_W2t[j] = __float2half(W2[k * 64 + n]);
    } else if (i < 64 * 128 + 64 * 64 + 256 * 64) {  // WPQt[n][k], n<256, k<64
        int j = i - (64 * 128 + 64 * 64);
        int n = j >> 6, k = j & 63;
        float v = (n < 128) ? fc1W[k * MHID + n] : fc1W[(64 + k) * MHID + (n - 128)];
        g_WPQt[j] = __float2half(v);
    }
}

// ---- GEMM1 (tensor core): g_hs = half((X[N,128] @ W1[128,64]) * dinv) ----
// block: 128 threads (4 warps), tile M=64, N=64, K=128
__global__ void __launch_bounds__(128) k_gemm1(const float* __restrict__ X) {
    __shared__ __half Xh[64][136];   // pitch 136 halves -> conflict-free frags
    __shared__ __half Wh[64][136];
    const int tid = threadIdx.x;
    const int base = blockIdx.x * 64;

    // stage Wt: 1024 uint4, 8 per thread; 16 uint4 per 128-half row
    #pragma unroll
    for (int it = 0; it < 8; it++) {
        int idx = tid + it * 128;
        int n = idx >> 4, c8 = idx & 15;
        *reinterpret_cast<uint4*>(&Wh[n][c8 * 8]) = reinterpret_cast<const uint4*>(g_W1t)[idx];
    }
    // stage X: 2048 float4, 16 per thread; 32 float4 per row
    #pragma unroll
    for (int it = 0; it < 16; it++) {
        int idx = tid + it * 128;
        int r = idx >> 5, c4 = idx & 31;
        int row = base + r;
        float4 v = make_float4(0.f, 0.f, 0.f, 0.f);
        if (row < NNODES) v = reinterpret_cast<const float4*>(X)[(size_t)row * 32 + c4];
        st_h4(&Xh[r][c4 * 4], v);
    }
    __syncthreads();

    const int warp = tid >> 5, lane = tid & 31;
    const int quad = lane >> 2, tq = lane & 3;
    const int rbase = warp * 16;

    float acc[8][4];
    #pragma unroll
    for (int nt = 0; nt < 8; nt++)
        #pragma unroll
        for (int c = 0; c < 4; c++) acc[nt][c] = 0.f;

    #pragma unroll
    for (int kt = 0; kt < 8; kt++) {
        int k0 = kt * 16;
        unsigned a0 = *reinterpret_cast<const unsigned*>(&Xh[rbase + quad][k0 + tq * 2]);
        unsigned a1 = *reinterpret_cast<const unsigned*>(&Xh[rbase + quad + 8][k0 + tq * 2]);
        unsigned a2 = *reinterpret_cast<const unsigned*>(&Xh[rbase + quad][k0 + 8 + tq * 2]);
        unsigned a3 = *reinterpret_cast<const unsigned*>(&Xh[rbase + quad + 8][k0 + 8 + tq * 2]);
        #pragma unroll
        for (int nt = 0; nt < 8; nt++) {
            unsigned b0 = *reinterpret_cast<const unsigned*>(&Wh[nt * 8 + quad][k0 + tq * 2]);
            unsigned b1 = *reinterpret_cast<const unsigned*>(&Wh[nt * 8 + quad][k0 + 8 + tq * 2]);
            mma16816(acc[nt], a0, a1, a2, a3, b0, b1);
        }
    }

    int r0 = base + rbase + quad;
    int r1 = r0 + 8;
    float d0 = (r0 < NNODES) ? g_dinv[r0] : 0.f;
    float d1 = (r1 < NNODES) ? g_dinv[r1] : 0.f;
    #pragma unroll
    for (int nt = 0; nt < 8; nt++) {
        int n = nt * 8 + tq * 2;
        if (r0 < NNODES) {
            __half2 h = __floats2half2_rn(acc[nt][0] * d0, acc[nt][1] * d0);
            *reinterpret_cast<__half2*>(&g_hs[(size_t)r0 * 64 + n]) = h;
        }
        if (r1 < NNODES) {
            __half2 h = __floats2half2_rn(acc[nt][2] * d1, acc[nt][3] * d1);
            *reinterpret_cast<__half2*>(&g_hs[(size_t)r1 * 64 + n]) = h;
        }
    }
}

// ---- GEMM2 (tensor core): g_hs = half((g_bufC[N,64] @ W2[64,64]) * dinv) ----
__global__ void __launch_bounds__(128) k_gemm2() {
    __shared__ __half Xh[64][72];
    __shared__ __half Wh[64][72];
    const int tid = threadIdx.x;
    const int base = blockIdx.x * 64;

    // Wt: 512 uint4, 4 per thread; 8 uint4 per 64-half row
    #pragma unroll
    for (int it = 0; it < 4; it++) {
        int idx = tid + it * 128;
        int n = idx >> 3, c8 = idx & 7;
        *reinterpret_cast<uint4*>(&Wh[n][c8 * 8]) = reinterpret_cast<const uint4*>(g_W2t)[idx];
    }
    // X = g_bufC: 1024 float4, 8 per thread; 16 float4 per row
    #pragma unroll
    for (int it = 0; it < 8; it++) {
        int idx = tid + it * 128;
        int r = idx >> 4, c4 = idx & 15;
        int row = base + r;
        float4 v = make_float4(0.f, 0.f, 0.f, 0.f);
        if (row < NNODES) v = reinterpret_cast<const float4*>(g_bufC)[(size_t)row * 16 + c4];
        st_h4(&Xh[r][c4 * 4], v);
    }
    __syncthreads();

    const int warp = tid >> 5, lane = tid & 31;
    const int quad = lane >> 2, tq = lane & 3;
    const int rbase = warp * 16;

    float acc[8][4];
    #pragma unroll
    for (int nt = 0; nt < 8; nt++)
        #pragma unroll
        for (int c = 0; c < 4; c++) acc[nt][c] = 0.f;

    #pragma unroll
    for (int kt = 0; kt < 4; kt++) {
        int k0 = kt * 16;
        unsigned a0 = *reinterpret_cast<const unsigned*>(&Xh[rbase + quad][k0 + tq * 2]);
        unsigned a1 = *reinterpret_cast<const unsigned*>(&Xh[rbase + quad + 8][k0 + tq * 2]);
        unsigned a2 = *reinterpret_cast<const unsigned*>(&Xh[rbase + quad][k0 + 8 + tq * 2]);
        unsigned a3 = *reinterpret_cast<const unsigned*>(&Xh[rbase + quad + 8][k0 + 8 + tq * 2]);
        #pragma unroll
        for (int nt = 0; nt < 8; nt++) {
            unsigned b0 = *reinterpret_cast<const unsigned*>(&Wh[nt * 8 + quad][k0 + tq * 2]);
            unsigned b1 = *reinterpret_cast<const unsigned*>(&Wh[nt * 8 + quad][k0 + 8 + tq * 2]);
            mma16816(acc[nt], a0, a1, a2, a3, b0, b1);
        }
    }

    int r0 = base + rbase + quad;
    int r1 = r0 + 8;
    float d0 = (r0 < NNODES) ? g_dinv[r0] : 0.f;
    float d1 = (r1 < NNODES) ? g_dinv[r1] : 0.f;
    #pragma unroll
    for (int nt = 0; nt < 8; nt++) {
        int n = nt * 8 + tq * 2;
        if (r0 < NNODES) {
            __half2 h = __floats2half2_rn(acc[nt][0] * d0, acc[nt][1] * d0);
            *reinterpret_cast<__half2*>(&g_hs[(size_t)r0 * 64 + n]) = h;
        }
        if (r1 < NNODES) {
            __half2 h = __floats2half2_rn(acc[nt][2] * d1, acc[nt][3] * d1);
            *reinterpret_cast<__half2*>(&g_hs[(size_t)r1 * 64 + n]) = h;
        }
    }
}

// ---- aggregation: out[v] = act(dinv[v] * (hs[v] + sum_{u->v} hs[u]) + b) ----
template <int DO_RELU>
__global__ void __launch_bounds__(256) k_agg(const float* __restrict__ bias) {
    const uint2* hs = reinterpret_cast<const uint2*>(g_hs);
    float4* out4 = reinterpret_cast<float4*>(g_bufC);
    int v = blockIdx.x * 16 + (threadIdx.x >> 4);
    int l = threadIdx.x & 15;
    if (v >= NNODES) return;
    int cnt = min(g_cnt[v], ELLW);
    const int4* ep4 = reinterpret_cast<const int4*>(&g_ell[(size_t)v * ELLW]);

    float4 acc = unpack_h4(hs[(size_t)v * 16 + l]);
    int n4 = cnt >> 2;
    for (int q = 0; q < n4; q++) {
        int4 ss = ep4[q];
        float4 b0 = unpack_h4(hs[(size_t)ss.x * 16 + l]);
        float4 b1 = unpack_h4(hs[(size_t)ss.y * 16 + l]);
        float4 b2 = unpack_h4(hs[(size_t)ss.z * 16 + l]);
        float4 b3 = unpack_h4(hs[(size_t)ss.w * 16 + l]);
        acc.x += (b0.x + b1.x) + (b2.x + b3.x);
        acc.y += (b0.y + b1.y) + (b2.y + b3.y);
        acc.z += (b0.z + b1.z) + (b2.z + b3.z);
        acc.w += (b0.w + b1.w) + (b2.w + b3.w);
    }
    const int* ep = &g_ell[(size_t)v * ELLW];
    for (int n = n4 << 2; n < cnt; n++) {
        float4 b0 = unpack_h4(hs[(size_t)ep[n] * 16 + l]);
        acc.x += b0.x; acc.y += b0.y; acc.z += b0.z; acc.w += b0.w;
    }
    float dv = g_dinv[v];
    float4 bb = reinterpret_cast<const float4*>(bias)[l];
    float4 r;
    r.x = fmaf(dv, acc.x, bb.x);
    r.y = fmaf(dv, acc.y, bb.y);
    r.z = fmaf(dv, acc.z, bb.z);
    r.w = fmaf(dv, acc.w, bb.w);
    if (DO_RELU) {
        r.x = fmaxf(r.x, 0.f); r.y = fmaxf(r.y, 0.f);
        r.z = fmaxf(r.z, 0.f); r.w = fmaxf(r.w, 0.f);
    }
    out4[(size_t)v * 16 + l] = r;
}

// ---- fused PQ (tensor core): [P|Q] = out[N,64] @ WPQt^T[64,256] ----
// block: 128 threads (4 warps), tile M=32, N=256 (warp w covers n=w*64..w*64+63)
__global__ void __launch_bounds__(128) k_gemmPQ(const float* __restrict__ fc1b) {
    __shared__ __half Xh[32][72];
    __shared__ __half Wh[256][72];
    const int tid = threadIdx.x;
    const int base = blockIdx.x * 32;   // 100000 = 32*3125 exact

    // Wt: 2048 uint4, 16 per thread; 8 uint4 per 64-half row
    #pragma unroll
    for (int it = 0; it < 16; it++) {
        int idx = tid + it * 128;
        int n = idx >> 3, c8 = idx & 7;
        *reinterpret_cast<uint4*>(&Wh[n][c8 * 8]) = reinterpret_cast<const uint4*>(g_WPQt)[idx];
    }
    // X = g_bufC: 512 float4, 4 per thread
    #pragma unroll
    for (int it = 0; it < 4; it++) {
        int idx = tid + it * 128;
        int r = idx >> 4, c4 = idx & 15;
        float4 v = reinterpret_cast<const float4*>(g_bufC)[(size_t)(base + r) * 16 + c4];
        st_h4(&Xh[r][c4 * 4], v);
    }
    __syncthreads();

    const int warp = tid >> 5, lane = tid & 31;
    const int quad = lane >> 2, tq = lane & 3;
    const int n0w = warp * 64;

    float acc[2][8][4];
    #pragma unroll
    for (int mt = 0; mt < 2; mt++)
        #pragma unroll
        for (int nt = 0; nt < 8; nt++)
            #pragma unroll
            for (int c = 0; c < 4; c++) acc[mt][nt][c] = 0.f;

    #pragma unroll
    for (int kt = 0; kt < 4; kt++) {
        int k0 = kt * 16;
        #pragma unroll
        for (int mt = 0; mt < 2; mt++) {
            int rb = mt * 16;
            unsigned a0 = *reinterpret_cast<const unsigned*>(&Xh[rb + quad][k0 + tq * 2]);
            unsigned a1 = *reinterpret_cast<const unsigned*>(&Xh[rb + quad + 8][k0 + tq * 2]);
            unsigned a2 = *reinterpret_cast<const unsigned*>(&Xh[rb + quad][k0 + 8 + tq * 2]);
            unsigned a3 = *reinterpret_cast<const unsigned*>(&Xh[rb + quad + 8][k0 + 8 + tq * 2]);
            #pragma unroll
            for (int nt = 0; nt < 8; nt++) {
                unsigned b0 = *reinterpret_cast<const unsigned*>(&Wh[n0w + nt * 8 + quad][k0 + tq * 2]);
                unsigned b1 = *reinterpret_cast<const unsigned*>(&Wh[n0w + nt * 8 + quad][k0 + 8 + tq * 2]);
                mma16816(acc[mt][nt], a0, a1, a2, a3, b0, b1);
            }
        }
    }

    #pragma unroll
    for (int mt = 0; mt < 2; mt++) {
        int r0 = base + mt * 16 + quad;
        int r1 = r0 + 8;
        #pragma unroll
        for (int nt = 0; nt < 8; nt++) {
            int ng = n0w + nt * 8 + tq * 2;      // global concat column
            float bias0 = 0.f, bias1 = 0.f;
            if (ng < MHID) { bias0 = fc1b[ng]; bias1 = fc1b[ng + 1]; }
            __half2 h0 = __floats2half2_rn(acc[mt][nt][0] + bias0, acc[mt][nt][1] + bias1);
            __half2 h1 = __floats2half2_rn(acc[mt][nt][2] + bias0, acc[mt][nt][3] + bias1);
            if (ng < MHID) {
                *reinterpret_cast<__half2*>(&g_P[(size_t)r0 * MHID + ng]) = h0;
                *reinterpret_cast<__half2*>(&g_P[(size_t)r1 * MHID + ng]) = h1;
            } else {
                *reinterpret_cast<__half2*>(&g_Q[(size_t)r0 * MHID + (ng - MHID)]) = h0;
                *reinterpret_cast<__half2*>(&g_Q[(size_t)r1 * MHID + (ng - MHID)]) = h1;
            }
        }
    }
}

// ---- query: res = relu(P[i] + Q[j]) @ fc2_W + fc2_b ----
__global__ void __launch_bounds__(256) k_query(const int* __restrict__ qi,
                                               const int* __restrict__ qj,
                                               const float* __restrict__ fc2W,
                                               const float* __restrict__ fc2b,
                                               float* __restrict__ outp, int Q) {
    __shared__ float w2s[MHID * 2];
    int tid = threadIdx.x;
    w2s[tid] = fc2W[tid];
    __syncthreads();

    int warp = (blockIdx.x * blockDim.x + tid) >> 5;
    int lane = tid & 31;
    if (warp >= Q) return;
    int i = qi[warp];
    int j = qj[warp];
    float4 p = unpack_h4(reinterpret_cast<const uint2*>(g_P)[(size_t)i * 32 + lane]);
    float4 q = unpack_h4(reinterpret_cast<const uint2*>(g_Q)[(size_t)j * 32 + lane]);

    float a0 = 0.f, a1 = 0.f;
    int c = lane * 4;
    float h;
    h = fmaxf(p.x + q.x, 0.f); a0 = fmaf(h, w2s[(c+0)*2], a0); a1 = fmaf(h, w2s[(c+0)*2+1], a1);
    h = fmaxf(p.y + q.y, 0.f); a0 = fmaf(h, w2s[(c+1)*2], a0); a1 = fmaf(h, w2s[(c+1)*2+1], a1);
    h = fmaxf(p.z + q.z, 0.f); a0 = fmaf(h, w2s[(c+2)*2], a0); a1 = fmaf(h, w2s[(c+2)*2+1], a1);
    h = fmaxf(p.w + q.w, 0.f); a0 = fmaf(h, w2s[(c+3)*2], a0); a1 = fmaf(h, w2s[(c+3)*2+1], a1);

    #pragma unroll
    for (int off = 16; off > 0; off >>= 1) {
        a0 += __shfl_xor_sync(0xffffffffu, a0, off);
        a1 += __shfl_xor_sync(0xffffffffu, a1, off);
    }
    if (lane == 0) {
        outp[(size_t)warp * 2 + 0] = a0 + fc2b[0];
        outp[(size_t)warp * 2 + 1] = a1 + fc2b[1];
    }
}

extern "C" void kernel_launch(void* const* d_in, const int* in_sizes, int n_in,
                              void* d_out, int out_size) {
    const float* feature = (const float*)d_in[0];
    const int*   edges   = (const int*)  d_in[1];
    const int*   qi      = (const int*)  d_in[2];
    const int*   qj      = (const int*)  d_in[3];
    const float* W1      = (const float*)d_in[4];
    const float* b1      = (const float*)d_in[5];
    const float* W2      = (const float*)d_in[6];
    const float* b2      = (const float*)d_in[7];
    const float* fc1W    = (const float*)d_in[8];
    const float* fc1b    = (const float*)d_in[9];
    const float* fc2W    = (const float*)d_in[10];
    const float* fc2b    = (const float*)d_in[11];
    float* outp = (float*)d_out;

    const int E = in_sizes[1] / 2;
    const int Q = in_sizes[2];
    const int* es = edges;
    const int* ed = edges + E;

    k_zero<<<(NNODES + 255) / 256, 256>>>();
    k_prep<<<112, 256>>>(W1, W2, fc1W);
    k_fill<<<(E + 255) / 256, 256>>>(es, ed, E);
    k_dinv<<<(NNODES + 255) / 256, 256>>>();

    // layer 1: tensor-core gemm -> gather-agg (+relu)
    k_gemm1<<<(NNODES + 63) / 64, 128>>>(feature);
    k_agg<1><<<(NNODES + 15) / 16, 256>>>(b1);

    // layer 2: tensor-core gemm -> gather-agg (no relu)
    k_gemm2<<<(NNODES + 63) / 64, 128>>>();
    k_agg<0><<<(NNODES + 15) / 16, 256>>>(b2);

    // fused per-node MLP halves (tensor core, fp16 outputs)
    k_gemmPQ<<<NNODES / 32, 128>>>(fc1b);

    // queries
    k_query<<<(Q + 7) / 8, 256>>>(qi, qj, fc2W, fc2b, outp, Q);
}

// round 9
// speedup vs baseline: 1.0059x; 1.0059x over previous
#include <cuda_runtime.h>
#include <cuda_fp16.h>
#include <cstdint>

#define NNODES 100000
#define FIN    128
#define FHID   64
#define MHID   128
#define ELLW   96

__device__ int    g_cnt[NNODES];
__device__ int    g_ell[(size_t)NNODES * ELLW];
__device__ float  g_dinv[NNODES];
__device__ __align__(16) __half g_hs[NNODES * FHID];     // gemm outputs, pre-scaled, fp16
__device__ float  g_bufC[NNODES * FHID];                 // h1 / out (fp32)
__device__ __align__(16) __half g_P[(size_t)NNODES * MHID];
__device__ __align__(16) __half g_Q[(size_t)NNODES * MHID];
// transposed fp16 weights: [n][k]
__device__ __align__(16) __half g_W1t[64 * 128];
__device__ __align__(16) __half g_W2t[64 * 64];
__device__ __align__(16) __half g_WPQt[256 * 64];

__device__ __forceinline__ float4 unpack_h4(uint2 u) {
    __half2 lo = *reinterpret_cast<__half2*>(&u.x);
    __half2 hi = *reinterpret_cast<__half2*>(&u.y);
    float2 a = __half22float2(lo);
    float2 b = __half22float2(hi);
    return make_float4(a.x, a.y, b.x, b.y);
}

__device__ __forceinline__ void mma16816(float d[4],
                                         unsigned a0, unsigned a1, unsigned a2, unsigned a3,
                                         unsigned b0, unsigned b1) {
    asm volatile("mma.sync.aligned.m16n8k16.row.col.f32.f16.f16.f32 "
                 "{%0,%1,%2,%3}, {%4,%5,%6,%7}, {%8,%9}, {%0,%1,%2,%3};"
                 : "+f"(d[0]), "+f"(d[1]), "+f"(d[2]), "+f"(d[3])
                 : "r"(a0), "r"(a1), "r"(a2), "r"(a3), "r"(b0), "r"(b1));
}

// store float4 as 2x half2 (8 bytes) to smem
__device__ __forceinline__ void st_h4(__half* p, float4 v) {
    __half2 lo = __floats2half2_rn(v.x, v.y);
    __half2 hi = __floats2half2_rn(v.z, v.w);
    uint2 u;
    u.x = *reinterpret_cast<unsigned*>(&lo);
    u.y = *reinterpret_cast<unsigned*>(&hi);
    *reinterpret_cast<uint2*>(p) = u;
}

// ---- setup ----
__global__ void k_zero() {
    int i = blockIdx.x * blockDim.x + threadIdx.x;
    if (i < NNODES) g_cnt[i] = 0;
}

__global__ void k_fill(const int* __restrict__ src, const int* __restrict__ dst, int E) {
    int e = blockIdx.x * blockDim.x + threadIdx.x;
    if (e >= E) return;
    int s = src[e], d = dst[e];
    int pos = atomicAdd(&g_cnt[d], 1);
    if (pos < ELLW) g_ell[(size_t)d * ELLW + pos] = s;
}

__global__ void k_dinv() {
    int v = blockIdx.x * blockDim.x + threadIdx.x;
    if (v < NNODES) g_dinv[v] = rsqrtf(fmaxf((float)(g_cnt[v] + 1), 1e-12f));
}

// ---- convert+transpose weights to fp16 [n][k] ----
__global__ void k_prep(const float* __restrict__ W1, const float* __restrict__ W2,
                       const float* __restrict__ fc1W) {
    int i = blockIdx.x * blockDim.x + threadIdx.x;
    if (i < 64 * 128) {                          // W1t[n][k], n<64, k<128
        int n = i >> 7, k = i & 127;
        g_W1t[i] = __float2half(W1[k * 64 + n]);
    } else if (i < 64 * 128 + 64 * 64) {         // W2t[n][k], n<64, k<64
        int j = i - 64 * 128;
        int n = j >> 6, k = j & 63;
        g_W2t[j] = __float2half(W2[k * 64 + n]);
    } else if (i < 64 * 128 + 64 * 64 + 256 * 64) {  // WPQt[n][k], n<256, k<64
        int j = i - (64 * 128 + 64 * 64);
        int n = j >> 6, k = j & 63;
        float v = (n < 128) ? fc1W[k * MHID + n] : fc1W[(64 + k) * MHID + (n - 128)];
        g_WPQt[j] = __float2half(v);
    }
}

// ---- GEMM1 (tensor core): g_hs = half((X[N,128] @ W1[128,64]) * dinv) ----
// block: 128 threads (4 warps), tile M=64, N=64, K=128
__global__ void __launch_bounds__(128) k_gemm1(const float* __restrict__ X) {
    __shared__ __half Xh[64][136];   // pitch 136 halves -> conflict-free frags
    __shared__ __half Wh[64][136];
    const int tid = threadIdx.x;
    const int base = blockIdx.x * 64;

    // stage Wt: 1024 uint4, 8 per thread; 16 uint4 per 128-half row
    #pragma unroll
    for (int it = 0; it < 8; it++) {
        int idx = tid + it * 128;
        int n = idx >> 4, c8 = idx & 15;
        *reinterpret_cast<uint4*>(&Wh[n][c8 * 8]) = reinterpret_cast<const uint4*>(g_W1t)[idx];
    }
    // stage X: 2048 float4, 16 per thread; 32 float4 per row
    #pragma unroll
    for (int it = 0; it < 16; it++) {
        int idx = tid + it * 128;
        int r = idx >> 5, c4 = idx & 31;
        int row = base + r;
        float4 v = make_float4(0.f, 0.f, 0.f, 0.f);
        if (row < NNODES) v = reinterpret_cast<const float4*>(X)[(size_t)row * 32 + c4];
        st_h4(&Xh[r][c4 * 4], v);
    }
    __syncthreads();

    const int warp = tid >> 5, lane = tid & 31;
    const int quad = lane >> 2, tq = lane & 3;
    const int rbase = warp * 16;

    float acc[8][4];
    #pragma unroll
    for (int nt = 0; nt < 8; nt++)
        #pragma unroll
        for (int c = 0; c < 4; c++) acc[nt][c] = 0.f;

    #pragma unroll
    for (int kt = 0; kt < 8; kt++) {
        int k0 = kt * 16;
        unsigned a0 = *reinterpret_cast<const unsigned*>(&Xh[rbase + quad][k0 + tq * 2]);
        unsigned a1 = *reinterpret_cast<const unsigned*>(&Xh[rbase + quad + 8][k0 + tq * 2]);
        unsigned a2 = *reinterpret_cast<const unsigned*>(&Xh[rbase + quad][k0 + 8 + tq * 2]);
        unsigned a3 = *reinterpret_cast<const unsigned*>(&Xh[rbase + quad + 8][k0 + 8 + tq * 2]);
        #pragma unroll
        for (int nt = 0; nt < 8; nt++) {
            unsigned b0 = *reinterpret_cast<const unsigned*>(&Wh[nt * 8 + quad][k0 + tq * 2]);
            unsigned b1 = *reinterpret_cast<const unsigned*>(&Wh[nt * 8 + quad][k0 + 8 + tq * 2]);
            mma16816(acc[nt], a0, a1, a2, a3, b0, b1);
        }
    }

    int r0 = base + rbase + quad;
    int r1 = r0 + 8;
    float d0 = (r0 < NNODES) ? g_dinv[r0] : 0.f;
    float d1 = (r1 < NNODES) ? g_dinv[r1] : 0.f;
    #pragma unroll
    for (int nt = 0; nt < 8; nt++) {
        int n = nt * 8 + tq * 2;
        if (r0 < NNODES) {
            __half2 h = __floats2half2_rn(acc[nt][0] * d0, acc[nt][1] * d0);
            *reinterpret_cast<__half2*>(&g_hs[(size_t)r0 * 64 + n]) = h;
        }
        if (r1 < NNODES) {
            __half2 h = __floats2half2_rn(acc[nt][2] * d1, acc[nt][3] * d1);
            *reinterpret_cast<__half2*>(&g_hs[(size_t)r1 * 64 + n]) = h;
        }
    }
}

// ---- GEMM2 (tensor core): g_hs = half((g_bufC[N,64] @ W2[64,64]) * dinv) ----
__global__ void __launch_bounds__(128) k_gemm2() {
    __shared__ __half Xh[64][72];
    __shared__ __half Wh[64][72];
    const int tid = threadIdx.x;
    const int base = blockIdx.x * 64;

    // Wt: 512 uint4, 4 per thread; 8 uint4 per 64-half row
    #pragma unroll
    for (int it = 0; it < 4; it++) {
        int idx = tid + it * 128;
        int n = idx >> 3, c8 = idx & 7;
        *reinterpret_cast<uint4*>(&Wh[n][c8 * 8]) = reinterpret_cast<const uint4*>(g_W2t)[idx];
    }
    // X = g_bufC: 1024 float4, 8 per thread; 16 float4 per row
    #pragma unroll
    for (int it = 0; it < 8; it++) {
        int idx = tid + it * 128;
        int r = idx >> 4, c4 = idx & 15;
        int row = base + r;
        float4 v = make_float4(0.f, 0.f, 0.f, 0.f);
        if (row < NNODES) v = reinterpret_cast<const float4*>(g_bufC)[(size_t)row * 16 + c4];
        st_h4(&Xh[r][c4 * 4], v);
    }
    __syncthreads();

    const int warp = tid >> 5, lane = tid & 31;
    const int quad = lane >> 2, tq = lane & 3;
    const int rbase = warp * 16;

    float acc[8][4];
    #pragma unroll
    for (int nt = 0; nt < 8; nt++)
        #pragma unroll
        for (int c = 0; c < 4; c++) acc[nt][c] = 0.f;

    #pragma unroll
    for (int kt = 0; kt < 4; kt++) {
        int k0 = kt * 16;
        unsigned a0 = *reinterpret_cast<const unsigned*>(&Xh[rbase + quad][k0 + tq * 2]);
        unsigned a1 = *reinterpret_cast<const unsigned*>(&Xh[rbase + quad + 8][k0 + tq * 2]);
        unsigned a2 = *reinterpret_cast<const unsigned*>(&Xh[rbase + quad][k0 + 8 + tq * 2]);
        unsigned a3 = *reinterpret_cast<const unsigned*>(&Xh[rbase + quad + 8][k0 + 8 + tq * 2]);
        #pragma unroll
        for (int nt = 0; nt < 8; nt++) {
            unsigned b0 = *reinterpret_cast<const unsigned*>(&Wh[nt * 8 + quad][k0 + tq * 2]);
            unsigned b1 = *reinterpret_cast<const unsigned*>(&Wh[nt * 8 + quad][k0 + 8 + tq * 2]);
            mma16816(acc[nt], a0, a1, a2, a3, b0, b1);
        }
    }

    int r0 = base + rbase + quad;
    int r1 = r0 + 8;
    float d0 = (r0 < NNODES) ? g_dinv[r0] : 0.f;
    float d1 = (r1 < NNODES) ? g_dinv[r1] : 0.f;
    #pragma unroll
    for (int nt = 0; nt < 8; nt++) {
        int n = nt * 8 + tq * 2;
        if (r0 < NNODES) {
            __half2 h = __floats2half2_rn(acc[nt][0] * d0, acc[nt][1] * d0);
            *reinterpret_cast<__half2*>(&g_hs[(size_t)r0 * 64 + n]) = h;
        }
        if (r1 < NNODES) {
            __half2 h = __floats2half2_rn(acc[nt][2] * d1, acc[nt][3] * d1);
            *reinterpret_cast<__half2*>(&g_hs[(size_t)r1 * 64 + n]) = h;
        }
    }
}

// ---- aggregation: out[v] = act(dinv[v] * (hs[v] + sum_{u->v} hs[u]) + b) ----
template <int DO_RELU>
__global__ void __launch_bounds__(256) k_agg(const float* __restrict__ bias) {
    const uint2* hs = reinterpret_cast<const uint2*>(g_hs);
    float4* out4 = reinterpret_cast<float4*>(g_bufC);
    int v = blockIdx.x * 16 + (threadIdx.x >> 4);
    int l = threadIdx.x & 15;
    if (v >= NNODES) return;
    int cnt = min(g_cnt[v], ELLW);
    const int4* ep4 = reinterpret_cast<const int4*>(&g_ell[(size_t)v * ELLW]);

    float4 acc = unpack_h4(hs[(size_t)v * 16 + l]);
    int n4 = cnt >> 2;
    for (int q = 0; q < n4; q++) {
        int4 ss = ep4[q];
        float4 b0 = unpack_h4(hs[(size_t)ss.x * 16 + l]);
        float4 b1 = unpack_h4(hs[(size_t)ss.y * 16 + l]);
        float4 b2 = unpack_h4(hs[(size_t)ss.z * 16 + l]);
        float4 b3 = unpack_h4(hs[(size_t)ss.w * 16 + l]);
        acc.x += (b0.x + b1.x) + (b2.x + b3.x);
        acc.y += (b0.y + b1.y) + (b2.y + b3.y);
        acc.z += (b0.z + b1.z) + (b2.z + b3.z);
        acc.w += (b0.w + b1.w) + (b2.w + b3.w);
    }
    const int* ep = &g_ell[(size_t)v * ELLW];
    for (int n = n4 << 2; n < cnt; n++) {
        float4 b0 = unpack_h4(hs[(size_t)ep[n] * 16 + l]);
        acc.x += b0.x; acc.y += b0.y; acc.z += b0.z; acc.w += b0.w;
    }
    float dv = g_dinv[v];
    float4 bb = reinterpret_cast<const float4*>(bias)[l];
    float4 r;
    r.x = fmaf(dv, acc.x, bb.x);
    r.y = fmaf(dv, acc.y, bb.y);
    r.z = fmaf(dv, acc.z, bb.z);
    r.w = fmaf(dv, acc.w, bb.w);
    if (DO_RELU) {
        r.x = fmaxf(r.x, 0.f); r.y = fmaxf(r.y, 0.f);
        r.z = fmaxf(r.z, 0.f); r.w = fmaxf(r.w, 0.f);
    }
    out4[(size_t)v * 16 + l] = r;
}

// ---- fused PQ (tensor core): [P|Q] = out[N,64] @ WPQt^T[64,256] ----
// block: 128 threads (4 warps), tile M=32, N=256 (warp w covers n=w*64..w*64+63)
__global__ void __launch_bounds__(128) k_gemmPQ(const float* __restrict__ fc1b) {
    __shared__ __half Xh[32][72];
    __shared__ __half Wh[256][72];
    const int tid = threadIdx.x;
    const int base = blockIdx.x * 32;   // 100000 = 32*3125 exact

    // Wt: 2048 uint4, 16 per thread; 8 uint4 per 64-half row
    #pragma unroll
    for (int it = 0; it < 16; it++) {
        int idx = tid + it * 128;
        int n = idx >> 3, c8 = idx & 7;
        *reinterpret_cast<uint4*>(&Wh[n][c8 * 8]) = reinterpret_cast<const uint4*>(g_WPQt)[idx];
    }
    // X = g_bufC: 512 float4, 4 per thread
    #pragma unroll
    for (int it = 0; it < 4; it++) {
        int idx = tid + it * 128;
        int r = idx >> 4, c4 = idx & 15;
        float4 v = reinterpret_cast<const float4*>(g_bufC)[(size_t)(base + r) * 16 + c4];
        st_h4(&Xh[r][c4 * 4], v);
    }
    __syncthreads();

    const int warp = tid >> 5, lane = tid & 31;
    const int quad = lane >> 2, tq = lane & 3;
    const int n0w = warp * 64;

    float acc[2][8][4];
    #pragma unroll
    for (int mt = 0; mt < 2; mt++)
        #pragma unroll
        for (int nt = 0; nt < 8; nt++)
            #pragma unroll
            for (int c = 0; c < 4; c++) acc[mt][nt][c] = 0.f;

    #pragma unroll
    for (int kt = 0; kt < 4; kt++) {
        int k0 = kt * 16;
        #pragma unroll
        for (int mt = 0; mt < 2; mt++) {
            int rb = mt * 16;
            unsigned a0 = *reinterpret_cast<const unsigned*>(&Xh[rb + quad][k0 + tq * 2]);
            unsigned a1 = *reinterpret_cast<const unsigned*>(&Xh[rb + quad + 8][k0 + tq * 2]);
            unsigned a2 = *reinterpret_cast<const unsigned*>(&Xh[rb + quad][k0 + 8 + tq * 2]);
            unsigned a3 = *reinterpret_cast<const unsigned*>(&Xh[rb + quad + 8][k0 + 8 + tq * 2]);
            #pragma unroll
            for (int nt = 0; nt < 8; nt++) {
                unsigned b0 = *reinterpret_cast<const unsigned*>(&Wh[n0w + nt * 8 + quad][k0 + tq * 2]);
                unsigned b1 = *reinterpret_cast<const unsigned*>(&Wh[n0w + nt * 8 + quad][k0 + 8 + tq * 2]);
                mma16816(acc[mt][nt], a0, a1, a2, a3, b0, b1);
            }
        }
    }

    #pragma unroll
    for (int mt = 0; mt < 2; mt++) {
        int r0 = base + mt * 16 + quad;
        int r1 = r0 + 8;
        #pragma unroll
        for (int nt = 0; nt < 8; nt++) {
            int ng = n0w + nt * 8 + tq * 2;      // global concat column
            float bias0 = 0.f, bias1 = 0.f;
            if (ng < MHID) { bias0 = fc1b[ng]; bias1 = fc1b[ng + 1]; }
            __half2 h0 = __floats2half2_rn(acc[mt][nt][0] + bias0, acc[mt][nt][1] + bias1);
            __half2 h1 = __floats2half2_rn(acc[mt][nt][2] + bias0, acc[mt][nt][3] + bias1);
            if (ng < MHID) {
                *reinterpret_cast<__half2*>(&g_P[(size_t)r0 * MHID + ng]) = h0;
                *reinterpret_cast<__half2*>(&g_P[(size_t)r1 * MHID + ng]) = h1;
            } else {
                *reinterpret_cast<__half2*>(&g_Q[(size_t)r0 * MHID + (ng - MHID)]) = h0;
                *reinterpret_cast<__half2*>(&g_Q[(size_t)r1 * MHID + (ng - MHID)]) = h1;
            }
        }
    }
}

// ---- query: res = relu(P[i] + Q[j]) @ fc2_W + fc2_b ----
__global__ void __launch_bounds__(256) k_query(const int* __restrict__ qi,
                                               const int* __restrict__ qj,
                                               const float* __restrict__ fc2W,
                                               const float* __restrict__ fc2b,
                                               float* __restrict__ outp, int Q) {
    __shared__ float w2s[MHID * 2];
    int tid = threadIdx.x;
    w2s[tid] = fc2W[tid];
    __syncthreads();

    int warp = (blockIdx.x * blockDim.x + tid) >> 5;
    int lane = tid & 31;
    if (warp >= Q) return;
    int i = qi[warp];
    int j = qj[warp];
    float4 p = unpack_h4(reinterpret_cast<const uint2*>(g_P)[(size_t)i * 32 + lane]);
    float4 q = unpack_h4(reinterpret_cast<const uint2*>(g_Q)[(size_t)j * 32 + lane]);

    float a0 = 0.f, a1 = 0.f;
    int c = lane * 4;
    float h;
    h = fmaxf(p.x + q.x, 0.f); a0 = fmaf(h, w2s[(c+0)*2], a0); a1 = fmaf(h, w2s[(c+0)*2+1], a1);
    h = fmaxf(p.y + q.y, 0.f); a0 = fmaf(h, w2s[(c+1)*2], a0); a1 = fmaf(h, w2s[(c+1)*2+1], a1);
    h = fmaxf(p.z + q.z, 0.f); a0 = fmaf(h, w2s[(c+2)*2], a0); a1 = fmaf(h, w2s[(c+2)*2+1], a1);
    h = fmaxf(p.w + q.w, 0.f); a0 = fmaf(h, w2s[(c+3)*2], a0); a1 = fmaf(h, w2s[(c+3)*2+1], a1);

    #pragma unroll
    for (int off = 16; off > 0; off >>= 1) {
        a0 += __shfl_xor_sync(0xffffffffu, a0, off);
        a1 += __shfl_xor_sync(0xffffffffu, a1, off);
    }
    if (lane == 0) {
        outp[(size_t)warp * 2 + 0] = a0 + fc2b[0];
        outp[(size_t)warp * 2 + 1] = a1 + fc2b[1];
    }
}

extern "C" void kernel_launch(void* const* d_in, const int* in_sizes, int n_in,
                              void* d_out, int out_size) {
    const float* feature = (const float*)d_in[0];
    const int*   edges   = (const int*)  d_in[1];
    const int*   qi      = (const int*)  d_in[2];
    const int*   qj      = (const int*)  d_in[3];
    const float* W1      = (const float*)d_in[4];
    const float* b1      = (const float*)d_in[5];
    const float* W2      = (const float*)d_in[6];
    const float* b2      = (const float*)d_in[7];
    const float* fc1W    = (const float*)d_in[8];
    const float* fc1b    = (const float*)d_in[9];
    const float* fc2W    = (const float*)d_in[10];
    const float* fc2b    = (const float*)d_in[11];
    float* outp = (float*)d_out;

    const int E = in_sizes[1] / 2;
    const int Q = in_sizes[2];
    const int* es = edges;
    const int* ed = edges + E;

    k_zero<<<(NNODES + 255) / 256, 256>>>();
    k_prep<<<112, 256>>>(W1, W2, fc1W);
    k_fill<<<(E + 255) / 256, 256>>>(es, ed, E);
    k_dinv<<<(NNODES + 255) / 256, 256>>>();

    // layer 1: tensor-core gemm -> gather-agg (+relu)
    k_gemm1<<<(NNODES + 63) / 64, 128>>>(feature);
    k_agg<1><<<(NNODES + 15) / 16, 256>>>(b1);

    // layer 2: tensor-core gemm -> gather-agg (no relu)
    k_gemm2<<<(NNODES + 63) / 64, 128>>>();
    k_agg<0><<<(NNODES + 15) / 16, 256>>>(b2);

    // fused per-node MLP halves (tensor core, fp16 outputs)
    k_gemmPQ<<<NNODES / 32, 128>>>(fc1b);

    // queries
    k_query<<<(Q + 7) / 8, 256>>>(qi, qj, fc2W, fc2b, outp, Q);
}